// round 4
// baseline (speedup 1.0000x reference)
#include <cuda_runtime.h>
#include <math.h>
#include <stdint.h>

#define D_MODEL   1024
#define HIDDEN    4096
#define N_EXPERTS 8
#define T_TOKENS  16384
#define MAX_ROWS  (T_TOKENS * 2)

// tile config
#define TILE_M 128
#define TILE_N 128
#define TBK    32
#define PADF   36                 // padded row stride in floats
#define ROWB   144                // bytes
#define MBUF   (128 * ROWB)       // 18432 B per matrix per stage
#define STAGEB (2 * MBUF)         // 36864 B per stage (A then B)
#define NSTAGE 3
#define SMEM_TOTAL (NSTAGE * STAGEB)   // 110592 B

// ---------------- scratch ----------------
__device__ int   g_count[N_EXPERTS];
__device__ int   g_offset[N_EXPERTS];
__device__ int   g_tok[N_EXPERTS * T_TOKENS];
__device__ float g_wt [N_EXPERTS * T_TOKENS];
__device__ float g_h  [(size_t)MAX_ROWS * HIDDEN];            // tf32-rounded h
__device__ float g_xr [(size_t)T_TOKENS * D_MODEL];           // tf32-rounded x
__device__ float g_w1t[(size_t)N_EXPERTS * HIDDEN * D_MODEL]; // [E][N=4096][K=1024]
__device__ float g_w2t[(size_t)N_EXPERTS * D_MODEL * HIDDEN]; // [E][N=1024][K=4096]

// ---------------- helpers ----------------
__device__ __forceinline__ uint32_t smem_u32(const void* p) {
    uint32_t a;
    asm("{ .reg .u64 t; cvta.to.shared.u64 t, %1; cvt.u32.u64 %0, t; }" : "=r"(a) : "l"(p));
    return a;
}
__device__ __forceinline__ float to_tf32(float f) {
    uint32_t u;
    asm("cvt.rna.tf32.f32 %0, %1;" : "=r"(u) : "f"(f));
    return __uint_as_float(u);
}
#define CP_ASYNC16(dst, src) \
    asm volatile("cp.async.cg.shared.global [%0], [%1], 16;" :: "r"(dst), "l"(src))
#define CP_COMMIT() asm volatile("cp.async.commit_group;" ::: "memory")
#define CP_WAIT1()  asm volatile("cp.async.wait_group 1;" ::: "memory")
#define CP_WAIT0()  asm volatile("cp.async.wait_group 0;" ::: "memory")

#define LDSM_X4(r0, r1, r2, r3, addr) \
    asm volatile("ldmatrix.sync.aligned.m8n8.x4.shared.b16 {%0,%1,%2,%3}, [%4];" \
        : "=r"(r0), "=r"(r1), "=r"(r2), "=r"(r3) : "r"(addr))

__device__ __forceinline__ void mma_tf32(float* d, const uint32_t* a, const uint32_t* b) {
    asm volatile(
        "mma.sync.aligned.m16n8k8.row.col.f32.tf32.tf32.f32 "
        "{%0,%1,%2,%3}, {%4,%5,%6,%7}, {%8,%9}, {%0,%1,%2,%3};"
        : "+f"(d[0]), "+f"(d[1]), "+f"(d[2]), "+f"(d[3])
        : "r"(a[0]), "r"(a[1]), "r"(a[2]), "r"(a[3]), "r"(b[0]), "r"(b[1]));
}
#define RED_ADD_V2(ptr, v0, v1) \
    asm volatile("red.global.add.v2.f32 [%0], {%1, %2};" :: "l"(ptr), "f"(v0), "f"(v1) : "memory")

// ---------------- kernel 0: zero output + counters ----------------
__global__ void zero_kernel(float4* out, int n4) {
    int i = blockIdx.x * blockDim.x + threadIdx.x;
    if (i < n4) out[i] = make_float4(0.f, 0.f, 0.f, 0.f);
    if (i < N_EXPERTS) g_count[i] = 0;
}

// ---------------- kernel 0c: transpose weights (+ tf32 round) ----------------
__global__ void transpose_w_kernel(const float* __restrict__ w1, const float* __restrict__ w2) {
    __shared__ float tile[32][33];
    const int z = blockIdx.z;
    const float* src; float* dst; int R, C;
    if (z < N_EXPERTS) {
        src = w1 + (size_t)z * D_MODEL * HIDDEN; dst = g_w1t + (size_t)z * HIDDEN * D_MODEL;
        R = D_MODEL; C = HIDDEN;
    } else {
        src = w2 + (size_t)(z - N_EXPERTS) * HIDDEN * D_MODEL;
        dst = g_w2t + (size_t)(z - N_EXPERTS) * D_MODEL * HIDDEN;
        R = HIDDEN; C = D_MODEL;
    }
    const int c0 = blockIdx.x * 32, r0 = blockIdx.y * 32;
    if (c0 >= C || r0 >= R) return;
    const int tx = threadIdx.x, ty = threadIdx.y;
#pragma unroll
    for (int j = 0; j < 32; j += 8)
        tile[ty + j][tx] = to_tf32(src[(size_t)(r0 + ty + j) * C + c0 + tx]);
    __syncthreads();
#pragma unroll
    for (int j = 0; j < 32; j += 8)
        dst[(size_t)(c0 + ty + j) * R + r0 + tx] = tile[tx][ty + j];
}

// ---------------- kernel 1: gating (+ fused tf32 round of x) ----------------
__global__ void gate_kernel(const float* __restrict__ x, const float* __restrict__ gw) {
    int gtid = blockIdx.x * blockDim.x + threadIdx.x;
    int warp = gtid >> 5;
    int lane = gtid & 31;
    if (warp >= T_TOKENS) return;

    const float* xr = x + (size_t)warp * D_MODEL;
    float* xo = g_xr + (size_t)warp * D_MODEL;
    float acc[N_EXPERTS];
#pragma unroll
    for (int e = 0; e < N_EXPERTS; e++) acc[e] = 0.f;
    for (int d = lane; d < D_MODEL; d += 32) {
        float xv = xr[d];
        xo[d] = to_tf32(xv);
        float4 g0 = *(const float4*)(gw + d * N_EXPERTS);
        float4 g1 = *(const float4*)(gw + d * N_EXPERTS + 4);
        acc[0] += xv * g0.x; acc[1] += xv * g0.y; acc[2] += xv * g0.z; acc[3] += xv * g0.w;
        acc[4] += xv * g1.x; acc[5] += xv * g1.y; acc[6] += xv * g1.z; acc[7] += xv * g1.w;
    }
#pragma unroll
    for (int off = 16; off > 0; off >>= 1)
#pragma unroll
        for (int e = 0; e < N_EXPERTS; e++)
            acc[e] += __shfl_xor_sync(0xffffffffu, acc[e], off);

    if (lane == 0) {
        int i0 = 0; float m0 = acc[0];
#pragma unroll
        for (int e = 1; e < N_EXPERTS; e++) if (acc[e] > m0) { m0 = acc[e]; i0 = e; }
        int i1 = -1; float m1 = -1e30f;
#pragma unroll
        for (int e = 0; e < N_EXPERTS; e++) if (e != i0 && acc[e] > m1) { m1 = acc[e]; i1 = e; }
        float ex = expf(m1 - m0);
        float w0 = 1.0f / (1.0f + ex);
        float w1v = ex / (1.0f + ex);
        int p0 = atomicAdd(&g_count[i0], 1);
        g_tok[i0 * T_TOKENS + p0] = warp; g_wt[i0 * T_TOKENS + p0] = w0;
        int p1 = atomicAdd(&g_count[i1], 1);
        g_tok[i1 * T_TOKENS + p1] = warp; g_wt[i1 * T_TOKENS + p1] = w1v;
    }
}

__global__ void scan_kernel() {
    if (threadIdx.x == 0) {
        int s = 0;
        for (int e = 0; e < N_EXPERTS; e++) { g_offset[e] = s; s += g_count[e]; }
    }
}

// ============================================================================
// tf32 mma.sync grouped GEMM core: 3-stage cp.async pipeline + ldmatrix.
// A: gathered rows, K-major. B: transposed weights [N][K]. C tile 128x128.
// 256 threads = 8 warps (2M x 4N), warp tile 64x32 = 4x4 m16n8k8.
// ============================================================================
struct GemmCtx {
    const float* aptr[4];
    const float* bptr[4];
    uint32_t dA[4], dB[4];   // stage-0 smem byte addresses
};

__device__ __forceinline__ void gemm_issue(const GemmCtx& ctx, int kt, uint32_t soff) {
#pragma unroll
    for (int i = 0; i < 4; i++) {
        CP_ASYNC16(ctx.dA[i] + soff, ctx.aptr[i] + kt * TBK);
        CP_ASYNC16(ctx.dB[i] + soff, ctx.bptr[i] + kt * TBK);
    }
    CP_COMMIT();
}

__device__ __forceinline__ void gemm_mainloop(
    uint32_t sb, const GemmCtx& ctx, int NT,
    float acc[4][4][4], int wid, int lane)
{
    const int warpM = wid & 1, warpN = wid >> 1;
    const uint32_t th = ((uint32_t)(lane >> 3) & 1) * 8 + (lane & 7);  // row-in-tile
    const uint32_t tc = ((uint32_t)lane >> 4) * 16;                    // col-half bytes
    const uint32_t aoff = sb +        (warpM * 64 + th) * ROWB + tc;
    const uint32_t boff = sb + MBUF + (warpN * 32 + th) * ROWB + tc;

    // prologue: stages 0, 1
    gemm_issue(ctx, 0, 0);
    gemm_issue(ctx, 1, STAGEB);

    for (int kt = 0; kt < NT; kt++) {
        if (kt <= NT - 2) CP_WAIT1(); else CP_WAIT0();
        __syncthreads();
        if (kt + 2 < NT) gemm_issue(ctx, kt + 2, (uint32_t)((kt + 2) % NSTAGE) * STAGEB);

        const uint32_t so = (uint32_t)(kt % NSTAGE) * STAGEB;
        const uint32_t ab = aoff + so, bb = boff + so;
#pragma unroll
        for (int ks = 0; ks < 4; ks++) {
            uint32_t a[4][4], b[4][2];
#pragma unroll
            for (int mi = 0; mi < 4; mi++)
                LDSM_X4(a[mi][0], a[mi][1], a[mi][2], a[mi][3],
                        ab + (uint32_t)mi * 16 * ROWB + ks * 32);
            LDSM_X4(b[0][0], b[1][0], b[0][1], b[1][1], bb + ks * 32);
            LDSM_X4(b[2][0], b[3][0], b[2][1], b[3][1], bb + 16 * ROWB + ks * 32);
#pragma unroll
            for (int mi = 0; mi < 4; mi++)
#pragma unroll
                for (int ni = 0; ni < 4; ni++)
                    mma_tf32(acc[mi][ni], a[mi], b[ni]);
        }
    }
}

// ---------------- kernel 3: GEMM1 + SiLU -> g_h ----------------
// grid: (x = N-tiles fastest, y = M-tiles, z = expert)
__global__ void __launch_bounds__(256, 2)
gemm1_mma() {
    const int e     = blockIdx.z;
    const int mcnt  = g_count[e];
    const int mbase = blockIdx.y * TILE_M;
    if (mbase >= mcnt) return;
    const int nbase = blockIdx.x * TILE_N;

    extern __shared__ char smem_raw[];
    const uint32_t sb = smem_u32(smem_raw);
    const int tid = threadIdx.x, wid = tid >> 5, lane = tid & 31;
    const int hoff = g_offset[e];

    GemmCtx ctx;
    {
        const int r0 = tid >> 3, q = tid & 7;
        const float* Wt = g_w1t + (size_t)e * HIDDEN * D_MODEL;
        const int* tks = g_tok + e * T_TOKENS;
#pragma unroll
        for (int i = 0; i < 4; i++) {
            int r = r0 + 32 * i;
            int gm = mbase + r; if (gm >= mcnt) gm = mcnt - 1;
            ctx.aptr[i] = g_xr + (size_t)tks[gm] * D_MODEL + q * 4;
            ctx.bptr[i] = Wt + (size_t)(nbase + r) * D_MODEL + q * 4;
            ctx.dA[i] = sb + r * ROWB + q * 16;
            ctx.dB[i] = sb + MBUF + r * ROWB + q * 16;
        }
    }

    float acc[4][4][4];
#pragma unroll
    for (int mi = 0; mi < 4; mi++)
#pragma unroll
        for (int ni = 0; ni < 4; ni++)
#pragma unroll
            for (int k = 0; k < 4; k++) acc[mi][ni][k] = 0.f;

    gemm_mainloop(sb, ctx, D_MODEL / TBK, acc, wid, lane);

    // epilogue: SiLU + tf32 round -> g_h
    const int warpM = wid & 1, warpN = wid >> 1;
    const int rb = mbase + warpM * 64 + (lane >> 2);
    const int cb = nbase + warpN * 32 + (lane & 3) * 2;
#pragma unroll
    for (int mi = 0; mi < 4; mi++) {
#pragma unroll
        for (int half = 0; half < 2; half++) {
            const int gm = rb + mi * 16 + half * 8;
            if (gm < mcnt) {
                float* hp = g_h + (size_t)(hoff + gm) * HIDDEN + cb;
#pragma unroll
                for (int ni = 0; ni < 4; ni++) {
                    float v0 = acc[mi][ni][half * 2];
                    float v1 = acc[mi][ni][half * 2 + 1];
                    v0 = to_tf32(v0 / (1.0f + __expf(-v0)));
                    v1 = to_tf32(v1 / (1.0f + __expf(-v1)));
                    *(float2*)(hp + ni * 8) = make_float2(v0, v1);
                }
            }
        }
    }
}

// ---------------- kernel 4: GEMM2 + weighted scatter (red.v2) ----------------
__global__ void __launch_bounds__(256, 2)
gemm2_mma(float* __restrict__ out) {
    const int e     = blockIdx.z;
    const int mcnt  = g_count[e];
    const int mbase = blockIdx.y * TILE_M;
    if (mbase >= mcnt) return;
    const int nbase = blockIdx.x * TILE_N;

    extern __shared__ char smem_raw[];
    const uint32_t sb = smem_u32(smem_raw);
    const int tid = threadIdx.x, wid = tid >> 5, lane = tid & 31;
    const int hoff = g_offset[e];

    GemmCtx ctx;
    {
        const int r0 = tid >> 3, q = tid & 7;
        const float* Wt = g_w2t + (size_t)e * D_MODEL * HIDDEN;
#pragma unroll
        for (int i = 0; i < 4; i++) {
            int r = r0 + 32 * i;
            int gm = mbase + r; if (gm >= mcnt) gm = mcnt - 1;
            ctx.aptr[i] = g_h + (size_t)(hoff + gm) * HIDDEN + q * 4;
            ctx.bptr[i] = Wt + (size_t)(nbase + r) * HIDDEN + q * 4;
            ctx.dA[i] = sb + r * ROWB + q * 16;
            ctx.dB[i] = sb + MBUF + r * ROWB + q * 16;
        }
    }

    float acc[4][4][4];
#pragma unroll
    for (int mi = 0; mi < 4; mi++)
#pragma unroll
        for (int ni = 0; ni < 4; ni++)
#pragma unroll
            for (int k = 0; k < 4; k++) acc[mi][ni][k] = 0.f;

    gemm_mainloop(sb, ctx, HIDDEN / TBK, acc, wid, lane);

    // epilogue: weighted vector-red scatter-add into out
    const int warpM = wid & 1, warpN = wid >> 1;
    const int rb = mbase + warpM * 64 + (lane >> 2);
    const int cb = nbase + warpN * 32 + (lane & 3) * 2;
    const int* tks = g_tok + e * T_TOKENS;
    const float* wts = g_wt + e * T_TOKENS;
#pragma unroll
    for (int mi = 0; mi < 4; mi++) {
#pragma unroll
        for (int half = 0; half < 2; half++) {
            const int gm = rb + mi * 16 + half * 8;
            if (gm < mcnt) {
                const int tok = tks[gm];
                const float w = wts[gm];
                float* op = out + (size_t)tok * D_MODEL + cb;
#pragma unroll
                for (int ni = 0; ni < 4; ni++)
                    RED_ADD_V2(op + ni * 8, w * acc[mi][ni][half * 2],
                                            w * acc[mi][ni][half * 2 + 1]);
            }
        }
    }
}

// ---------------- launch ----------------
extern "C" void kernel_launch(void* const* d_in, const int* in_sizes, int n_in,
                              void* d_out, int out_size) {
    const float* x  = (const float*)d_in[0];
    const float* gw = (const float*)d_in[1];
    const float* w1 = (const float*)d_in[2];
    const float* w2 = (const float*)d_in[3];
    float* out = (float*)d_out;

    static bool attr_done = false;
    if (!attr_done) {
        cudaFuncSetAttribute(gemm1_mma, cudaFuncAttributeMaxDynamicSharedMemorySize, SMEM_TOTAL);
        cudaFuncSetAttribute(gemm2_mma, cudaFuncAttributeMaxDynamicSharedMemorySize, SMEM_TOTAL);
        attr_done = true;
    }

    int n4 = out_size / 4;
    zero_kernel<<<(n4 + 255) / 256, 256>>>((float4*)out, n4);
    {
        dim3 g(HIDDEN / 32, HIDDEN / 32, 2 * N_EXPERTS);
        transpose_w_kernel<<<g, dim3(32, 8)>>>(w1, w2);
    }
    gate_kernel<<<T_TOKENS / 8, 256>>>(x, gw);
    scan_kernel<<<1, 32>>>();

    // N-tiles fastest (x), M-tiles (y), expert (z): A tiles stay L2-resident
    dim3 g1(HIDDEN / TILE_N, T_TOKENS / TILE_M, N_EXPERTS);   // (32, 128, 8)
    gemm1_mma<<<g1, 256, SMEM_TOTAL>>>();

    dim3 g2(D_MODEL / TILE_N, T_TOKENS / TILE_M, N_EXPERTS);  // (8, 128, 8)
    gemm2_mma<<<g2, 256, SMEM_TOTAL>>>(out);
}

// round 5
// speedup vs baseline: 1.6525x; 1.6525x over previous
#include <cuda_runtime.h>
#include <cuda_fp16.h>
#include <math.h>
#include <stdint.h>

#define D_MODEL   1024
#define HIDDEN    4096
#define N_EXPERTS 8
#define T_TOKENS  16384
#define MAX_ROWS  (T_TOKENS * 2)

// tile config (fp16, m16n8k16)
#define TILE_M 128
#define TILE_N 128
#define TBK    32                 // K halfs per stage (64 B of data per row)
#define ROWH   80                 // padded row stride in bytes (40 halfs)
#define MBUF   (128 * ROWH)       // 10240 B per matrix per stage
#define STAGEB (2 * MBUF)         // 20480 B per stage
#define NSTAGE 3
#define SMEM_TOTAL (NSTAGE * STAGEB)   // 61440 B -> 2 CTAs/SM

// ---------------- scratch ----------------
__device__ int    g_count[N_EXPERTS];
__device__ int    g_offset[N_EXPERTS];
__device__ int    g_tok[N_EXPERTS * T_TOKENS];
__device__ float  g_wt [N_EXPERTS * T_TOKENS];
__device__ __half g_hh [(size_t)MAX_ROWS * HIDDEN];            // fp16 h (256 MB)
__device__ __half g_xh [(size_t)T_TOKENS * D_MODEL];           // fp16 x (32 MB)
__device__ __half g_w1h[(size_t)N_EXPERTS * HIDDEN * D_MODEL]; // [E][N=4096][K=1024] (64 MB)
__device__ __half g_w2h[(size_t)N_EXPERTS * D_MODEL * HIDDEN]; // [E][N=1024][K=4096] (64 MB)

// ---------------- helpers ----------------
__device__ __forceinline__ uint32_t smem_u32(const void* p) {
    uint32_t a;
    asm("{ .reg .u64 t; cvta.to.shared.u64 t, %1; cvt.u32.u64 %0, t; }" : "=r"(a) : "l"(p));
    return a;
}
#define CP_ASYNC16(dst, src) \
    asm volatile("cp.async.cg.shared.global [%0], [%1], 16;" :: "r"(dst), "l"(src))
#define CP_COMMIT() asm volatile("cp.async.commit_group;" ::: "memory")
#define CP_WAIT1()  asm volatile("cp.async.wait_group 1;" ::: "memory")
#define CP_WAIT0()  asm volatile("cp.async.wait_group 0;" ::: "memory")

#define LDSM_X4(r0, r1, r2, r3, addr) \
    asm volatile("ldmatrix.sync.aligned.m8n8.x4.shared.b16 {%0,%1,%2,%3}, [%4];" \
        : "=r"(r0), "=r"(r1), "=r"(r2), "=r"(r3) : "r"(addr))

__device__ __forceinline__ void mma_f16(float* d, const uint32_t* a, const uint32_t* b) {
    asm volatile(
        "mma.sync.aligned.m16n8k16.row.col.f32.f16.f16.f32 "
        "{%0,%1,%2,%3}, {%4,%5,%6,%7}, {%8,%9}, {%0,%1,%2,%3};"
        : "+f"(d[0]), "+f"(d[1]), "+f"(d[2]), "+f"(d[3])
        : "r"(a[0]), "r"(a[1]), "r"(a[2]), "r"(a[3]), "r"(b[0]), "r"(b[1]));
}
#define RED_ADD_V2(ptr, v0, v1) \
    asm volatile("red.global.add.v2.f32 [%0], {%1, %2};" :: "l"(ptr), "f"(v0), "f"(v1) : "memory")

// ---------------- kernel 0: zero output + counters ----------------
__global__ void zero_kernel(float4* out, int n4) {
    int i = blockIdx.x * blockDim.x + threadIdx.x;
    if (i < n4) out[i] = make_float4(0.f, 0.f, 0.f, 0.f);
    if (i < N_EXPERTS) g_count[i] = 0;
}

// ---------------- kernel 0c: transpose weights -> fp16 ----------------
__global__ void transpose_w_kernel(const float* __restrict__ w1, const float* __restrict__ w2) {
    __shared__ float tile[32][33];
    const int z = blockIdx.z;
    const float* src; __half* dst; int R, C;
    if (z < N_EXPERTS) {
        src = w1 + (size_t)z * D_MODEL * HIDDEN; dst = g_w1h + (size_t)z * HIDDEN * D_MODEL;
        R = D_MODEL; C = HIDDEN;
    } else {
        src = w2 + (size_t)(z - N_EXPERTS) * HIDDEN * D_MODEL;
        dst = g_w2h + (size_t)(z - N_EXPERTS) * D_MODEL * HIDDEN;
        R = HIDDEN; C = D_MODEL;
    }
    const int c0 = blockIdx.x * 32, r0 = blockIdx.y * 32;
    if (c0 >= C || r0 >= R) return;
    const int tx = threadIdx.x, ty = threadIdx.y;
#pragma unroll
    for (int j = 0; j < 32; j += 8)
        tile[ty + j][tx] = src[(size_t)(r0 + ty + j) * C + c0 + tx];
    __syncthreads();
#pragma unroll
    for (int j = 0; j < 32; j += 8)
        dst[(size_t)(c0 + ty + j) * R + r0 + tx] = __float2half_rn(tile[tx][ty + j]);
}

// ---------------- kernel 1: gating (+ fused fp16 cast of x) ----------------
__global__ void gate_kernel(const float* __restrict__ x, const float* __restrict__ gw) {
    int gtid = blockIdx.x * blockDim.x + threadIdx.x;
    int warp = gtid >> 5;
    int lane = gtid & 31;
    if (warp >= T_TOKENS) return;

    const float* xr = x + (size_t)warp * D_MODEL;
    __half* xo = g_xh + (size_t)warp * D_MODEL;
    float acc[N_EXPERTS];
#pragma unroll
    for (int e = 0; e < N_EXPERTS; e++) acc[e] = 0.f;
    for (int d = lane; d < D_MODEL; d += 32) {
        float xv = xr[d];
        xo[d] = __float2half_rn(xv);
        float4 g0 = *(const float4*)(gw + d * N_EXPERTS);
        float4 g1 = *(const float4*)(gw + d * N_EXPERTS + 4);
        acc[0] += xv * g0.x; acc[1] += xv * g0.y; acc[2] += xv * g0.z; acc[3] += xv * g0.w;
        acc[4] += xv * g1.x; acc[5] += xv * g1.y; acc[6] += xv * g1.z; acc[7] += xv * g1.w;
    }
#pragma unroll
    for (int off = 16; off > 0; off >>= 1)
#pragma unroll
        for (int e = 0; e < N_EXPERTS; e++)
            acc[e] += __shfl_xor_sync(0xffffffffu, acc[e], off);

    if (lane == 0) {
        int i0 = 0; float m0 = acc[0];
#pragma unroll
        for (int e = 1; e < N_EXPERTS; e++) if (acc[e] > m0) { m0 = acc[e]; i0 = e; }
        int i1 = -1; float m1 = -1e30f;
#pragma unroll
        for (int e = 0; e < N_EXPERTS; e++) if (e != i0 && acc[e] > m1) { m1 = acc[e]; i1 = e; }
        float ex = expf(m1 - m0);
        float w0 = 1.0f / (1.0f + ex);
        float w1v = ex / (1.0f + ex);
        int p0 = atomicAdd(&g_count[i0], 1);
        g_tok[i0 * T_TOKENS + p0] = warp; g_wt[i0 * T_TOKENS + p0] = w0;
        int p1 = atomicAdd(&g_count[i1], 1);
        g_tok[i1 * T_TOKENS + p1] = warp; g_wt[i1 * T_TOKENS + p1] = w1v;
    }
}

__global__ void scan_kernel() {
    if (threadIdx.x == 0) {
        int s = 0;
        for (int e = 0; e < N_EXPERTS; e++) { g_offset[e] = s; s += g_count[e]; }
    }
}

// ============================================================================
// fp16 mma.sync grouped GEMM core: 3-stage cp.async + ldmatrix + m16n8k16.
// A gathered rows (K-major), B transposed weights [N][K]. CTA tile 128x128.
// 256 threads = 8 warps (2M x 4N), warp tile 64x32 = 4x4 m16n8k16.
// ============================================================================
struct GemmCtx {
    const __half* a;   // this thread's A source (row, 16-half chunk pair base)
    const __half* b;   // this thread's B source
    uint32_t dA, dB;   // stage-0 smem dst byte addresses
};

__device__ __forceinline__ void gemm_issue(const GemmCtx& ctx, int kt, uint32_t soff) {
    const __half* a = ctx.a + kt * TBK;
    const __half* b = ctx.b + kt * TBK;
    CP_ASYNC16(ctx.dA + soff,      a);
    CP_ASYNC16(ctx.dA + soff + 16, a + 8);
    CP_ASYNC16(ctx.dB + soff,      b);
    CP_ASYNC16(ctx.dB + soff + 16, b + 8);
    CP_COMMIT();
}

__device__ __forceinline__ void gemm_mainloop(
    uint32_t sb, const GemmCtx& ctx, int NT,
    float acc[4][4][4], int wid, int lane)
{
    const int warpM = wid & 1, warpN = wid >> 1;
    // A ldmatrix addressing: lanes 0-7 rows 0-7 k0, 8-15 rows 8-15 k0,
    //                        16-23 rows 0-7 k8, 24-31 rows 8-15 k8
    const uint32_t rowA = (lane & 7) + ((lane >> 3) & 1) * 8;
    const uint32_t colA = ((uint32_t)lane >> 4) * 16;         // bytes
    // B ldmatrix addressing: lanes 0-7 n0-7 k0, 8-15 n0-7 k8,
    //                        16-23 n8-15 k0, 24-31 n8-15 k8
    const uint32_t rowB = (lane & 7) + (((uint32_t)lane >> 4) & 1) * 8;
    const uint32_t colB = (((uint32_t)lane >> 3) & 1) * 16;   // bytes
    const uint32_t aoff = sb +        (warpM * 64 + rowA) * ROWH + colA;
    const uint32_t boff = sb + MBUF + (warpN * 32 + rowB) * ROWH + colB;

    gemm_issue(ctx, 0, 0);
    gemm_issue(ctx, 1, STAGEB);

    for (int kt = 0; kt < NT; kt++) {
        if (kt <= NT - 2) CP_WAIT1(); else CP_WAIT0();
        __syncthreads();
        if (kt + 2 < NT) gemm_issue(ctx, kt + 2, (uint32_t)((kt + 2) % NSTAGE) * STAGEB);

        const uint32_t so = (uint32_t)(kt % NSTAGE) * STAGEB;
        const uint32_t ab = aoff + so, bb = boff + so;
#pragma unroll
        for (int ks = 0; ks < 2; ks++) {   // two k16 steps per K=32 stage
            uint32_t a[4][4], b[4][2];
#pragma unroll
            for (int mi = 0; mi < 4; mi++)
                LDSM_X4(a[mi][0], a[mi][1], a[mi][2], a[mi][3],
                        ab + (uint32_t)mi * 16 * ROWH + ks * 32);
            LDSM_X4(b[0][0], b[0][1], b[1][0], b[1][1], bb + ks * 32);
            LDSM_X4(b[2][0], b[2][1], b[3][0], b[3][1], bb + 16 * ROWH + ks * 32);
#pragma unroll
            for (int mi = 0; mi < 4; mi++)
#pragma unroll
                for (int ni = 0; ni < 4; ni++)
                    mma_f16(acc[mi][ni], a[mi], b[ni]);
        }
    }
}

// ---------------- kernel 3: GEMM1 + SiLU -> g_hh ----------------
// grid: (x = N-tiles fastest, y = M-tiles, z = expert)
__global__ void __launch_bounds__(256, 2)
gemm1_mma() {
    const int e     = blockIdx.z;
    const int mcnt  = g_count[e];
    const int mbase = blockIdx.y * TILE_M;
    if (mbase >= mcnt) return;
    const int nbase = blockIdx.x * TILE_N;

    extern __shared__ char smem_raw[];
    const uint32_t sb = smem_u32(smem_raw);
    const int tid = threadIdx.x, wid = tid >> 5, lane = tid & 31;
    const int hoff = g_offset[e];

    GemmCtx ctx;
    {
        const int r = tid >> 1, s = tid & 1;       // row 0-127, 16-half chunk pair
        int gm = mbase + r; if (gm >= mcnt) gm = mcnt - 1;
        ctx.a  = g_xh + (size_t)g_tok[e * T_TOKENS + gm] * D_MODEL + s * 16;
        ctx.b  = g_w1h + (size_t)e * HIDDEN * D_MODEL + (size_t)(nbase + r) * D_MODEL + s * 16;
        ctx.dA = sb + r * ROWH + s * 32;
        ctx.dB = sb + MBUF + r * ROWH + s * 32;
    }

    float acc[4][4][4];
#pragma unroll
    for (int mi = 0; mi < 4; mi++)
#pragma unroll
        for (int ni = 0; ni < 4; ni++)
#pragma unroll
            for (int k = 0; k < 4; k++) acc[mi][ni][k] = 0.f;

    gemm_mainloop(sb, ctx, D_MODEL / TBK, acc, wid, lane);

    // epilogue: SiLU -> fp16 h
    const int warpM = wid & 1, warpN = wid >> 1;
    const int rb = mbase + warpM * 64 + (lane >> 2);
    const int cb = nbase + warpN * 32 + (lane & 3) * 2;
#pragma unroll
    for (int mi = 0; mi < 4; mi++) {
#pragma unroll
        for (int half = 0; half < 2; half++) {
            const int gm = rb + mi * 16 + half * 8;
            if (gm < mcnt) {
                __half* hp = g_hh + (size_t)(hoff + gm) * HIDDEN + cb;
#pragma unroll
                for (int ni = 0; ni < 4; ni++) {
                    float v0 = acc[mi][ni][half * 2];
                    float v1 = acc[mi][ni][half * 2 + 1];
                    v0 = v0 / (1.0f + __expf(-v0));
                    v1 = v1 / (1.0f + __expf(-v1));
                    *(__half2*)(hp + ni * 8) = __floats2half2_rn(v0, v1);
                }
            }
        }
    }
}

// ---------------- kernel 4: GEMM2 + weighted scatter (red.v2) ----------------
__global__ void __launch_bounds__(256, 2)
gemm2_mma(float* __restrict__ out) {
    const int e     = blockIdx.z;
    const int mcnt  = g_count[e];
    const int mbase = blockIdx.y * TILE_M;
    if (mbase >= mcnt) return;
    const int nbase = blockIdx.x * TILE_N;

    extern __shared__ char smem_raw[];
    const uint32_t sb = smem_u32(smem_raw);
    const int tid = threadIdx.x, wid = tid >> 5, lane = tid & 31;
    const int hoff = g_offset[e];

    GemmCtx ctx;
    {
        const int r = tid >> 1, s = tid & 1;
        int gm = mbase + r; if (gm >= mcnt) gm = mcnt - 1;
        ctx.a  = g_hh + (size_t)(hoff + gm) * HIDDEN + s * 16;
        ctx.b  = g_w2h + (size_t)e * D_MODEL * HIDDEN + (size_t)(nbase + r) * HIDDEN + s * 16;
        ctx.dA = sb + r * ROWH + s * 32;
        ctx.dB = sb + MBUF + r * ROWH + s * 32;
    }

    float acc[4][4][4];
#pragma unroll
    for (int mi = 0; mi < 4; mi++)
#pragma unroll
        for (int ni = 0; ni < 4; ni++)
#pragma unroll
            for (int k = 0; k < 4; k++) acc[mi][ni][k] = 0.f;

    gemm_mainloop(sb, ctx, HIDDEN / TBK, acc, wid, lane);

    // epilogue: weighted vector-red scatter-add into out
    const int warpM = wid & 1, warpN = wid >> 1;
    const int rb = mbase + warpM * 64 + (lane >> 2);
    const int cb = nbase + warpN * 32 + (lane & 3) * 2;
    const int* tks = g_tok + e * T_TOKENS;
    const float* wts = g_wt + e * T_TOKENS;
#pragma unroll
    for (int mi = 0; mi < 4; mi++) {
#pragma unroll
        for (int half = 0; half < 2; half++) {
            const int gm = rb + mi * 16 + half * 8;
            if (gm < mcnt) {
                const int tok = tks[gm];
                const float w = wts[gm];
                float* op = out + (size_t)tok * D_MODEL + cb;
#pragma unroll
                for (int ni = 0; ni < 4; ni++)
                    RED_ADD_V2(op + ni * 8, w * acc[mi][ni][half * 2],
                                            w * acc[mi][ni][half * 2 + 1]);
            }
        }
    }
}

// ---------------- launch ----------------
extern "C" void kernel_launch(void* const* d_in, const int* in_sizes, int n_in,
                              void* d_out, int out_size) {
    const float* x  = (const float*)d_in[0];
    const float* gw = (const float*)d_in[1];
    const float* w1 = (const float*)d_in[2];
    const float* w2 = (const float*)d_in[3];
    float* out = (float*)d_out;

    static bool attr_done = false;
    if (!attr_done) {
        cudaFuncSetAttribute(gemm1_mma, cudaFuncAttributeMaxDynamicSharedMemorySize, SMEM_TOTAL);
        cudaFuncSetAttribute(gemm2_mma, cudaFuncAttributeMaxDynamicSharedMemorySize, SMEM_TOTAL);
        attr_done = true;
    }

    int n4 = out_size / 4;
    zero_kernel<<<(n4 + 255) / 256, 256>>>((float4*)out, n4);
    {
        dim3 g(HIDDEN / 32, HIDDEN / 32, 2 * N_EXPERTS);
        transpose_w_kernel<<<g, dim3(32, 8)>>>(w1, w2);
    }
    gate_kernel<<<T_TOKENS / 8, 256>>>(x, gw);
    scan_kernel<<<1, 32>>>();

    // N-tiles fastest (x): A tiles and B panels stay L2-resident per wave
    dim3 g1(HIDDEN / TILE_N, T_TOKENS / TILE_M, N_EXPERTS);   // (32, 128, 8)
    gemm1_mma<<<g1, 256, SMEM_TOTAL>>>();

    dim3 g2(D_MODEL / TILE_N, T_TOKENS / TILE_M, N_EXPERTS);  // (8, 128, 8)
    gemm2_mma<<<g2, 256, SMEM_TOTAL>>>(out);
}